// round 11
// baseline (speedup 1.0000x reference)
#include <cuda_runtime.h>

// Problem constants (match reference)
#define B_ 8
#define S_ 2048
#define N_ 512
#define D_ 1024
#define MAX_W_ 32
#define MASK_FILL_ (-1000.0f)

// Scratch for global attention logits (B*S floats = 64 KB).
__device__ float g_logits[B_ * S_];

// packed f32x2 FMA: acc = v * w + acc  (two floats at once)
__device__ __forceinline__ void fma2(unsigned long long& acc,
                                     unsigned long long v,
                                     unsigned long long w) {
    asm("fma.rn.f32x2 %0, %1, %2, %0;" : "+l"(acc) : "l"(v), "l"(w));
}
// broadcast one float into both halves of an f32x2 register pair
__device__ __forceinline__ unsigned long long pack2(float a) {
    unsigned long long r;
    asm("mov.b64 %0, {%1, %1};" : "=l"(r) : "r"(__float_as_uint(a)));
    return r;
}

// ---------------------------------------------------------------------------
// Kernel 1: logits[b,s] = dot(seq[b,s,:], att_w) + att_b. One warp per row.
__global__ void __launch_bounds__(256)
logits_kernel(const float* __restrict__ seq,
              const float* __restrict__ att_w,
              const float* __restrict__ att_b) {
    int warp = (blockIdx.x * blockDim.x + threadIdx.x) >> 5;
    int lane = threadIdx.x & 31;
    if (warp >= B_ * S_) return;

    const float4* row = reinterpret_cast<const float4*>(seq + (size_t)warp * D_);
    const float4* w4  = reinterpret_cast<const float4*>(att_w);

    float acc = 0.0f;
    #pragma unroll
    for (int i = 0; i < (D_ / 4) / 32; i++) {
        float4 a = row[lane + i * 32];
        float4 w = w4[lane + i * 32];
        acc += a.x * w.x + a.y * w.y + a.z * w.z + a.w * w.w;
    }
    #pragma unroll
    for (int off = 16; off; off >>= 1)
        acc += __shfl_xor_sync(0xffffffffu, acc, off);

    if (lane == 0)
        g_logits[warp] = acc + att_b[0];
}

// ---------------------------------------------------------------------------
// Kernel 2: one CTA (256 threads) per span; thread owns one 16B (4-float)
// column chunk. A row of D=1024 floats = 256 such chunks, so the chunk
// stride between consecutive rows is RCHUNK = D/4 = 256.
// Every warp computes the softmax redundantly (no smem, no __syncthreads, no
// serial warp0 prefix). Masked lanes contribute exp()==0 exactly, identical
// arithmetic to the reference. Pooling uses packed f32x2 FMAs; weight for
// ascending row j lives in lane (width - j) and is fetched by shuffle.
#define RCHUNK_ (D_ / 4)   // 16B chunks per row = 256

__global__ void __launch_bounds__(256)
span_kernel(const float* __restrict__ seq,
            const int*   __restrict__ spans,
            float*       __restrict__ out) {
    const int bn   = blockIdx.x;          // 0 .. B*N-1
    const int b    = bn >> 9;             // / N_ (N_ = 512)
    const int tid  = threadIdx.x;
    const int lane = tid & 31;

    const int start = __ldg(&spans[bn * 2 + 0]);
    const int end   = __ldg(&spans[bn * 2 + 1]);   // inclusive
    const int width = end - start;                 // 0..31
    const bool m    = (lane <= width);

    // --- per-warp softmax (lane t <-> position end - t) ---
    float logit = m ? g_logits[b * S_ + end - lane] : MASK_FILL_;
    float mx = logit;
    #pragma unroll
    for (int off = 16; off; off >>= 1)
        mx = fmaxf(mx, __shfl_xor_sync(0xffffffffu, mx, off));
    float e = m ? __expf(logit - mx) : 0.0f;
    float sum = e;
    #pragma unroll
    for (int off = 16; off; off >>= 1)
        sum += __shfl_xor_sync(0xffffffffu, sum, off);
    const float myattn = e / sum;   // weight of row (start + width - lane)

    // --- pooling: rows [start .. end], ascending ---
    const ulonglong2* base = reinterpret_cast<const ulonglong2*>(seq)
                           + ((size_t)b * S_ + start) * RCHUNK_ + tid;

    unsigned long long accx = 0ull, accy = 0ull;   // (c0,c1) and (c2,c3)

    const int nv = width + 1;
    int j = 0;
    for (; j + 4 <= nv; j += 4) {
        ulonglong2 v0 = base[(size_t)(j + 0) * RCHUNK_];
        ulonglong2 v1 = base[(size_t)(j + 1) * RCHUNK_];
        ulonglong2 v2 = base[(size_t)(j + 2) * RCHUNK_];
        ulonglong2 v3 = base[(size_t)(j + 3) * RCHUNK_];
        unsigned long long w0 = pack2(__shfl_sync(0xffffffffu, myattn, width - j));
        unsigned long long w1 = pack2(__shfl_sync(0xffffffffu, myattn, width - j - 1));
        unsigned long long w2 = pack2(__shfl_sync(0xffffffffu, myattn, width - j - 2));
        unsigned long long w3 = pack2(__shfl_sync(0xffffffffu, myattn, width - j - 3));
        fma2(accx, v0.x, w0); fma2(accy, v0.y, w0);
        fma2(accx, v1.x, w1); fma2(accy, v1.y, w1);
        fma2(accx, v2.x, w2); fma2(accy, v2.y, w2);
        fma2(accx, v3.x, w3); fma2(accy, v3.y, w3);
    }
    for (; j < nv; j++) {
        ulonglong2 v = base[(size_t)j * RCHUNK_];
        unsigned long long w = pack2(__shfl_sync(0xffffffffu, myattn, width - j));
        fma2(accx, v.x, w); fma2(accy, v.y, w);
    }

    ulonglong2 res;
    res.x = accx;
    res.y = accy;
    reinterpret_cast<ulonglong2*>(out)[(size_t)bn * RCHUNK_ + tid] = res;
}

// ---------------------------------------------------------------------------
extern "C" void kernel_launch(void* const* d_in, const int* in_sizes, int n_in,
                              void* d_out, int out_size) {
    const float* seq   = (const float*)d_in[0];   // (B, S, D) f32
    const int*   spans = (const int*)  d_in[1];   // (B, N, 2) i32
    const float* att_w = (const float*)d_in[2];   // (D, 1) f32
    const float* att_b = (const float*)d_in[3];   // (1,) f32
    float* out = (float*)d_out;                   // (B, N, D) f32

    logits_kernel<<<(B_ * S_) / 8, 256>>>(seq, att_w, att_b);
    span_kernel<<<B_ * N_, 256>>>(seq, spans, out);
}

// round 12
// speedup vs baseline: 1.0523x; 1.0523x over previous
#include <cuda_runtime.h>

// Problem constants (match reference)
#define B_ 8
#define S_ 2048
#define N_ 512
#define D_ 1024
#define MAX_W_ 32
#define MASK_FILL_ (-1000.0f)

// Scratch for global attention logits (B*S floats = 64 KB).
__device__ float g_logits[B_ * S_];

// packed f32x2 FMA: acc = v * w + acc  (two floats at once)
__device__ __forceinline__ void fma2(unsigned long long& acc,
                                     unsigned long long v,
                                     unsigned long long w) {
    asm("fma.rn.f32x2 %0, %1, %2, %0;" : "+l"(acc) : "l"(v), "l"(w));
}
// broadcast one float into both halves of an f32x2 register pair
__device__ __forceinline__ unsigned long long pack2(float a) {
    unsigned long long r;
    asm("mov.b64 %0, {%1, %1};" : "=l"(r) : "r"(__float_as_uint(a)));
    return r;
}

// ---------------------------------------------------------------------------
// Kernel 1: logits[b,s] = dot(seq[b,s,:], att_w) + att_b. One warp per row.
__global__ void __launch_bounds__(256)
logits_kernel(const float* __restrict__ seq,
              const float* __restrict__ att_w,
              const float* __restrict__ att_b) {
    int warp = (blockIdx.x * blockDim.x + threadIdx.x) >> 5;
    int lane = threadIdx.x & 31;
    if (warp >= B_ * S_) return;

    const float4* row = reinterpret_cast<const float4*>(seq + (size_t)warp * D_);
    const float4* w4  = reinterpret_cast<const float4*>(att_w);

    float acc = 0.0f;
    #pragma unroll
    for (int i = 0; i < (D_ / 4) / 32; i++) {
        float4 a = row[lane + i * 32];
        float4 w = w4[lane + i * 32];
        acc += a.x * w.x + a.y * w.y + a.z * w.z + a.w * w.w;
    }
    #pragma unroll
    for (int off = 16; off; off >>= 1)
        acc += __shfl_xor_sync(0xffffffffu, acc, off);

    if (lane == 0)
        g_logits[warp] = acc + att_b[0];
}

// ---------------------------------------------------------------------------
// Kernel 2: one CTA (256 threads) per span; thread owns one 16B (4-float)
// column chunk. A row of D=1024 floats = 256 such chunks, so the chunk
// stride between consecutive rows is RCHUNK = D/4 = 256.
// Every warp computes the softmax redundantly (no smem, no __syncthreads, no
// serial warp0 prefix). Masked lanes contribute exp()==0 exactly, identical
// arithmetic to the reference. Pooling uses packed f32x2 FMAs; weight for
// ascending row j lives in lane (width - j) and is fetched by shuffle.
#define RCHUNK_ (D_ / 4)   // 16B chunks per row = 256

__global__ void __launch_bounds__(256)
span_kernel(const float* __restrict__ seq,
            const int*   __restrict__ spans,
            float*       __restrict__ out) {
    const int bn   = blockIdx.x;          // 0 .. B*N-1
    const int b    = bn >> 9;             // / N_ (N_ = 512)
    const int tid  = threadIdx.x;
    const int lane = tid & 31;

    const int start = __ldg(&spans[bn * 2 + 0]);
    const int end   = __ldg(&spans[bn * 2 + 1]);   // inclusive
    const int width = end - start;                 // 0..31
    const bool m    = (lane <= width);

    // --- per-warp softmax (lane t <-> position end - t) ---
    float logit = m ? g_logits[b * S_ + end - lane] : MASK_FILL_;
    float mx = logit;
    #pragma unroll
    for (int off = 16; off; off >>= 1)
        mx = fmaxf(mx, __shfl_xor_sync(0xffffffffu, mx, off));
    float e = m ? __expf(logit - mx) : 0.0f;
    float sum = e;
    #pragma unroll
    for (int off = 16; off; off >>= 1)
        sum += __shfl_xor_sync(0xffffffffu, sum, off);
    const float myattn = e / sum;   // weight of row (start + width - lane)

    // --- pooling: rows [start .. end], ascending ---
    const ulonglong2* base = reinterpret_cast<const ulonglong2*>(seq)
                           + ((size_t)b * S_ + start) * RCHUNK_ + tid;

    unsigned long long accx = 0ull, accy = 0ull;   // (c0,c1) and (c2,c3)

    const int nv = width + 1;
    int j = 0;
    for (; j + 4 <= nv; j += 4) {
        ulonglong2 v0 = base[(size_t)(j + 0) * RCHUNK_];
        ulonglong2 v1 = base[(size_t)(j + 1) * RCHUNK_];
        ulonglong2 v2 = base[(size_t)(j + 2) * RCHUNK_];
        ulonglong2 v3 = base[(size_t)(j + 3) * RCHUNK_];
        unsigned long long w0 = pack2(__shfl_sync(0xffffffffu, myattn, width - j));
        unsigned long long w1 = pack2(__shfl_sync(0xffffffffu, myattn, width - j - 1));
        unsigned long long w2 = pack2(__shfl_sync(0xffffffffu, myattn, width - j - 2));
        unsigned long long w3 = pack2(__shfl_sync(0xffffffffu, myattn, width - j - 3));
        fma2(accx, v0.x, w0); fma2(accy, v0.y, w0);
        fma2(accx, v1.x, w1); fma2(accy, v1.y, w1);
        fma2(accx, v2.x, w2); fma2(accy, v2.y, w2);
        fma2(accx, v3.x, w3); fma2(accy, v3.y, w3);
    }
    for (; j < nv; j++) {
        ulonglong2 v = base[(size_t)j * RCHUNK_];
        unsigned long long w = pack2(__shfl_sync(0xffffffffu, myattn, width - j));
        fma2(accx, v.x, w); fma2(accy, v.y, w);
    }

    ulonglong2 res;
    res.x = accx;
    res.y = accy;
    reinterpret_cast<ulonglong2*>(out)[(size_t)bn * RCHUNK_ + tid] = res;
}

// ---------------------------------------------------------------------------
extern "C" void kernel_launch(void* const* d_in, const int* in_sizes, int n_in,
                              void* d_out, int out_size) {
    const float* seq   = (const float*)d_in[0];   // (B, S, D) f32
    const int*   spans = (const int*)  d_in[1];   // (B, N, 2) i32
    const float* att_w = (const float*)d_in[2];   // (D, 1) f32
    const float* att_b = (const float*)d_in[3];   // (1,) f32
    float* out = (float*)d_out;                   // (B, N, D) f32

    logits_kernel<<<(B_ * S_) / 8, 256>>>(seq, att_w, att_b);
    span_kernel<<<B_ * N_, 256>>>(seq, spans, out);
}